// round 1
// baseline (speedup 1.0000x reference)
#include <cuda_runtime.h>
#include <math.h>

#define SPARSITY_EPS 1e-05f
#define MAX_E 32
#define MAX_N 65536

// Per-token routing record: {e0 (as int bits), e1 (as int bits), w0, w1}
__device__ float4 g_rec[MAX_N];

// ---------------------------------------------------------------------------
// Kernel 1: gate logits (x @ W.T + b), top-2, softmax, s_concat, record.
// One block per token. One warp per expert (E <= warps in block).
// Dynamic smem: xs[D] | lg[E] | rc[4]
// ---------------------------------------------------------------------------
__global__ void gate_kernel(const float* __restrict__ x,
                            const float* __restrict__ W,
                            const float* __restrict__ b,
                            float* __restrict__ s_out,   // may be null
                            int D, int E)
{
    extern __shared__ float smem[];
    float* xs = smem;          // D floats
    float* lg = smem + D;      // E floats
    float* rc = lg + E;        // 4 floats

    const int n    = blockIdx.x;
    const int tid  = threadIdx.x;
    const int lane = tid & 31;
    const int wid  = tid >> 5;
    const int nw   = blockDim.x >> 5;

    // stage x row
    const float* xrow = x + (size_t)n * D;
    for (int i = tid; i < D; i += blockDim.x) xs[i] = xrow[i];
    __syncthreads();

    // each warp: dot(x, W[e,:]) + b[e]
    for (int e = wid; e < E; e += nw) {
        const float* wrow = W + (size_t)e * D;
        float acc = 0.f;
        for (int d = lane; d < D; d += 32)
            acc += xs[d] * __ldg(wrow + d);
        #pragma unroll
        for (int off = 16; off; off >>= 1)
            acc += __shfl_down_sync(0xffffffffu, acc, off);
        if (lane == 0) lg[e] = acc + __ldg(b + e);
    }
    __syncthreads();

    // thread 0: top-2 (ties -> lowest index, matching jax.lax.top_k) + softmax
    if (tid == 0) {
        int e0 = 0; float v0 = lg[0];
        for (int e = 1; e < E; e++)
            if (lg[e] > v0) { v0 = lg[e]; e0 = e; }
        int e1 = -1; float v1 = -INFINITY;
        for (int e = 0; e < E; e++)
            if (e != e0 && lg[e] > v1) { v1 = lg[e]; e1 = e; }
        // softmax over [v0, v1], v0 >= v1
        float ex = expf(v1 - v0);
        float w0 = 1.0f / (1.0f + ex);
        float w1 = ex / (1.0f + ex);
        float4 r = make_float4(__int_as_float(e0), __int_as_float(e1), w0, w1);
        g_rec[n] = r;
        rc[0] = r.x; rc[1] = r.y; rc[2] = r.z; rc[3] = r.w;
    }
    __syncthreads();

    // s_concat row: 1.0 where g < eps else 0.0
    if (s_out != nullptr && tid < E) {
        int e0 = __float_as_int(rc[0]);
        int e1 = __float_as_int(rc[1]);
        float g = 0.f;
        if (tid == e0) g = rc[2];
        else if (tid == e1) g = rc[3];
        s_out[(size_t)n * E + tid] = (g < SPARSITY_EPS) ? 1.0f : 0.0f;
    }
}

// ---------------------------------------------------------------------------
// Kernel 2: sparse combine  y[n,d] = w0*f[n,d,e0] + w1*f[n,d,e1]
// grid = (ceil(D/256), N), block = 256
// ---------------------------------------------------------------------------
__global__ void combine_kernel(const float* __restrict__ f,
                               float* __restrict__ y,
                               int D, int E)
{
    const int n = blockIdx.y;
    const int d = blockIdx.x * blockDim.x + threadIdx.x;
    if (d >= D) return;

    float4 r = g_rec[n];                       // L1-broadcast within block
    const int e0 = __float_as_int(r.x);
    const int e1 = __float_as_int(r.y);

    const float* fb = f + ((size_t)n * D + d) * E;
    y[(size_t)n * D + d] = r.z * __ldg(fb + e0) + r.w * __ldg(fb + e1);
}

// ---------------------------------------------------------------------------
// Kernel 3: deterministic reduction for soft/hard averages + tail zeroing.
// One block, 256 threads. E <= 16 assumed for shared sizing (E=16 here).
// ---------------------------------------------------------------------------
__global__ void reduce_kernel(float* __restrict__ soft_out,  // may be null
                              float* __restrict__ hard_out,
                              float* __restrict__ tail,      // may be null
                              int tail_n,
                              int N, int E)
{
    __shared__ float s_soft[256 * 16];
    __shared__ float s_hard[256 * 16];
    const int tid = threadIdx.x;
    const int Ec = (E <= 16) ? E : 16;

    if (soft_out != nullptr) {
        float lsoft[16], lhard[16];
        #pragma unroll
        for (int e = 0; e < 16; e++) { lsoft[e] = 0.f; lhard[e] = 0.f; }

        for (int n = tid; n < N; n += blockDim.x) {
            float4 r = g_rec[n];
            int e0 = __float_as_int(r.x);
            int e1 = __float_as_int(r.y);
            if (e0 < Ec) {
                lsoft[e0] += r.z;
                if (r.z >= SPARSITY_EPS) lhard[e0] += 1.f;
            }
            if (e1 < Ec) {
                lsoft[e1] += r.w;
                if (r.w >= SPARSITY_EPS) lhard[e1] += 1.f;
            }
        }
        for (int e = 0; e < Ec; e++) {
            s_soft[tid * 16 + e] = lsoft[e];
            s_hard[tid * 16 + e] = lhard[e];
        }
        __syncthreads();

        // fixed-order tree reduction (deterministic across replays)
        for (int str = blockDim.x >> 1; str > 0; str >>= 1) {
            if (tid < str) {
                for (int e = 0; e < Ec; e++) {
                    s_soft[tid * 16 + e] += s_soft[(tid + str) * 16 + e];
                    s_hard[tid * 16 + e] += s_hard[(tid + str) * 16 + e];
                }
            }
            __syncthreads();
        }
        if (tid < Ec) {
            float invN = 1.0f / (float)N;
            soft_out[tid] = s_soft[tid] * invN;
            hard_out[tid] = s_hard[tid] * invN;
        }
    }

    // zero any trailing output elements (the returned python scalar 0, padding)
    if (tail != nullptr) {
        for (int i = tid; i < tail_n; i += blockDim.x) tail[i] = 0.0f;
    }
}

// ---------------------------------------------------------------------------
extern "C" void kernel_launch(void* const* d_in, const int* in_sizes, int n_in,
                              void* d_out, int out_size)
{
    const float* f = (const float*)d_in[0];   // [N, D, E]
    const float* x = (const float*)d_in[1];   // [N, D]
    const float* W = (const float*)d_in[2];   // [E, D]
    const float* b = (const float*)d_in[3];   // [E]

    const int E = in_sizes[3];
    const int D = in_sizes[2] / E;
    const int N = in_sizes[1] / D;

    float* out = (float*)d_out;

    const long long y_elems    = (long long)N * D;
    const long long full_elems = y_elems + 2LL * E + (long long)N * E;

    const bool has_metrics = ((long long)out_size >= full_elems);

    float* y_ptr    = out;
    float* soft_ptr = has_metrics ? out + y_elems : nullptr;
    float* hard_ptr = has_metrics ? out + y_elems + E : nullptr;
    float* s_ptr    = has_metrics ? out + y_elems + 2 * E : nullptr;
    float* tail_ptr = nullptr;
    int    tail_n   = 0;
    if (has_metrics && (long long)out_size > full_elems) {
        tail_ptr = out + full_elems;
        tail_n   = (int)((long long)out_size - full_elems);
    } else if (!has_metrics && (long long)out_size > y_elems) {
        tail_ptr = out + y_elems;
        tail_n   = (int)((long long)out_size - y_elems);
    }

    // Kernel 1: gate
    {
        int threads = 512;
        size_t smem = (size_t)(D + E + 4) * sizeof(float);
        gate_kernel<<<N, threads, smem>>>(x, W, b, s_ptr, D, E);
    }

    // Kernel 2: combine
    {
        dim3 grid((D + 255) / 256, N);
        combine_kernel<<<grid, 256>>>(f, y_ptr, D, E);
    }

    // Kernel 3: reductions + tail
    if (has_metrics || tail_n > 0) {
        reduce_kernel<<<1, 256>>>(soft_ptr, hard_ptr, tail_ptr, tail_n, N, E);
    }
}

// round 3
// speedup vs baseline: 1.5166x; 1.5166x over previous
#include <cuda_runtime.h>
#include <math.h>

#define SPARSITY_EPS 1e-05f
#define MAX_N 65536

// Per-token routing record: {e0 (int bits), e1 (int bits), w0, w1}
__device__ float4 g_rec[MAX_N];

// ---------------------------------------------------------------------------
// Kernel 1: gate. One warp per token, 8 tokens per 256-thread block.
// W ([16,768] = 48KB) staged in shared memory once per block.
// Requires E==16, D % 128 == 0.
// ---------------------------------------------------------------------------
__global__ void gate_kernel(const float* __restrict__ x,
                            const float* __restrict__ W,
                            const float* __restrict__ b,
                            float* __restrict__ s_out,   // may be null
                            int D, int N)
{
    extern __shared__ float4 ws4[];          // [16 * D/4]
    const int tid  = threadIdx.x;
    const int lane = tid & 31;
    const int wid  = tid >> 5;
    const int D4   = D >> 2;

    // stage W as float4, coalesced
    const float4* Wg4 = (const float4*)W;
    for (int i = tid; i < 16 * D4; i += blockDim.x) ws4[i] = Wg4[i];
    __syncthreads();

    const int n = blockIdx.x * 8 + wid;
    if (n >= N) return;

    // accumulate 16 expert dots in registers
    float acc[16];
    #pragma unroll
    for (int e = 0; e < 16; e++) acc[e] = 0.f;

    const float4* xr = (const float4*)(x + (size_t)n * D);
    const int iters = D4 >> 5;               // D/128
    for (int i = 0; i < iters; i++) {
        const int q = lane + (i << 5);
        float4 xv = xr[q];
        #pragma unroll
        for (int e = 0; e < 16; e++) {
            float4 wv = ws4[e * D4 + q];
            acc[e] += xv.x * wv.x + xv.y * wv.y + xv.z * wv.z + xv.w * wv.w;
        }
    }

    // butterfly reduce all 16 accumulators across the warp
    #pragma unroll
    for (int off = 16; off; off >>= 1) {
        #pragma unroll
        for (int e = 0; e < 16; e++)
            acc[e] += __shfl_xor_sync(0xffffffffu, acc[e], off);
    }

    // lane 0: top-2 (ties -> lowest index, matches jax.lax.top_k) + softmax
    int e0 = 0, e1 = -1;
    float w0 = 0.f, w1 = 0.f;
    if (lane == 0) {
        float lg[16];
        #pragma unroll
        for (int e = 0; e < 16; e++) lg[e] = acc[e] + b[e];
        float v0 = lg[0]; e0 = 0;
        #pragma unroll
        for (int e = 1; e < 16; e++)
            if (lg[e] > v0) { v0 = lg[e]; e0 = e; }
        float v1 = -INFINITY;
        #pragma unroll
        for (int e = 0; e < 16; e++)
            if (e != e0 && lg[e] > v1) { v1 = lg[e]; e1 = e; }
        float ex = expf(v1 - v0);
        w0 = 1.0f / (1.0f + ex);
        w1 = ex / (1.0f + ex);
        g_rec[n] = make_float4(__int_as_float(e0), __int_as_float(e1), w0, w1);
    }

    // broadcast and write s_concat row (16 floats) from lanes 0..15
    e0 = __shfl_sync(0xffffffffu, e0, 0);
    e1 = __shfl_sync(0xffffffffu, e1, 0);
    w0 = __shfl_sync(0xffffffffu, w0, 0);
    w1 = __shfl_sync(0xffffffffu, w1, 0);
    if (s_out != nullptr && lane < 16) {
        float g = (lane == e0) ? w0 : ((lane == e1) ? w1 : 0.f);
        s_out[(size_t)n * 16 + lane] = (g < SPARSITY_EPS) ? 1.0f : 0.0f;
    }
}

// ---------------------------------------------------------------------------
// Kernel 2: dense coalesced combine. One block per token.
// y[n,d] = sum_e g[e] * f[n,d,e], read f as sequential float4 stream.
// Requires E==16.
// ---------------------------------------------------------------------------
__global__ void combine_kernel(const float* __restrict__ f,
                               float* __restrict__ y,
                               int D)
{
    __shared__ float4 gq[4];                 // gate vector as 4 quads
    const int n   = blockIdx.x;
    const int tid = threadIdx.x;

    if (tid < 16) ((float*)gq)[tid] = 0.f;
    __syncthreads();
    if (tid == 0) {
        float4 r = g_rec[n];
        ((float*)gq)[__float_as_int(r.x)] = r.z;
        ((float*)gq)[__float_as_int(r.y)] = r.w;
    }
    __syncthreads();

    const int total4 = D << 2;               // D*16/4 float4s
    const float4* fb = (const float4*)(f + (size_t)n * D * 16);
    float* yrow = y + (size_t)n * D;

    #pragma unroll 4
    for (int i = tid; i < total4; i += blockDim.x) {
        float4 fv = fb[i];
        float4 g  = gq[i & 3];
        float p = fv.x * g.x + fv.y * g.y + fv.z * g.z + fv.w * g.w;
        p += __shfl_xor_sync(0xffffffffu, p, 1);
        p += __shfl_xor_sync(0xffffffffu, p, 2);
        if ((tid & 3) == 0) yrow[i >> 2] = p;
    }
}

// ---------------------------------------------------------------------------
// Kernel 3: reductions for soft/hard averages + tail zeroing.
// One block, 1024 threads, fixed-order (deterministic) reduction.
// ---------------------------------------------------------------------------
__global__ void reduce_kernel(float* __restrict__ soft_out,  // may be null
                              float* __restrict__ hard_out,
                              float* __restrict__ tail,      // may be null
                              int tail_n, int N)
{
    __shared__ float s_soft[32 * 16];
    __shared__ float s_hard[32 * 16];
    const int tid  = threadIdx.x;
    const int lane = tid & 31;
    const int wid  = tid >> 5;

    if (soft_out != nullptr) {
        float lsoft[16], lhard[16];
        #pragma unroll
        for (int e = 0; e < 16; e++) { lsoft[e] = 0.f; lhard[e] = 0.f; }

        for (int n = tid; n < N; n += blockDim.x) {
            float4 r = g_rec[n];
            int e0 = __float_as_int(r.x);
            int e1 = __float_as_int(r.y);
            lsoft[e0] += r.z;
            if (r.z >= SPARSITY_EPS) lhard[e0] += 1.f;
            lsoft[e1] += r.w;
            if (r.w >= SPARSITY_EPS) lhard[e1] += 1.f;
        }
        // warp-level butterfly
        #pragma unroll
        for (int off = 16; off; off >>= 1) {
            #pragma unroll
            for (int e = 0; e < 16; e++) {
                lsoft[e] += __shfl_xor_sync(0xffffffffu, lsoft[e], off);
                lhard[e] += __shfl_xor_sync(0xffffffffu, lhard[e], off);
            }
        }
        if (lane == 0) {
            #pragma unroll
            for (int e = 0; e < 16; e++) {
                s_soft[wid * 16 + e] = lsoft[e];
                s_hard[wid * 16 + e] = lhard[e];
            }
        }
        __syncthreads();
        if (tid < 16) {
            float ss = 0.f, hh = 0.f;
            const int nw = blockDim.x >> 5;
            for (int w = 0; w < nw; w++) {      // fixed order: deterministic
                ss += s_soft[w * 16 + tid];
                hh += s_hard[w * 16 + tid];
            }
            float invN = 1.0f / (float)N;
            soft_out[tid] = ss * invN;
            hard_out[tid] = hh * invN;
        }
    }

    if (tail != nullptr) {
        for (int i = tid; i < tail_n; i += blockDim.x) tail[i] = 0.0f;
    }
}

// ---------------------------------------------------------------------------
extern "C" void kernel_launch(void* const* d_in, const int* in_sizes, int n_in,
                              void* d_out, int out_size)
{
    const float* f = (const float*)d_in[0];   // [N, D, E]
    const float* x = (const float*)d_in[1];   // [N, D]
    const float* W = (const float*)d_in[2];   // [E, D]
    const float* b = (const float*)d_in[3];   // [E]

    const int E = in_sizes[3];                // 16
    const int D = in_sizes[2] / E;            // 768
    const int N = in_sizes[1] / D;            // 8192

    float* out = (float*)d_out;

    const long long y_elems    = (long long)N * D;
    const long long full_elems = y_elems + 2LL * E + (long long)N * E;
    const bool has_metrics = ((long long)out_size >= full_elems);

    float* y_ptr    = out;
    float* soft_ptr = has_metrics ? out + y_elems : nullptr;
    float* hard_ptr = has_metrics ? out + y_elems + E : nullptr;
    float* s_ptr    = has_metrics ? out + y_elems + 2 * E : nullptr;
    float* tail_ptr = nullptr;
    int    tail_n   = 0;
    if (has_metrics && (long long)out_size > full_elems) {
        tail_ptr = out + full_elems;
        tail_n   = (int)((long long)out_size - full_elems);
    } else if (!has_metrics && (long long)out_size > y_elems) {
        tail_ptr = out + y_elems;
        tail_n   = (int)((long long)out_size - y_elems);
    }

    // Kernel 1: gate (W in dynamic smem: 16*D*4 = 48KB for D=768, within
    // the default dynamic-smem limit -> no attribute call needed)
    {
        size_t smem = (size_t)(16 * D) * sizeof(float);
        int blocks = (N + 7) / 8;
        gate_kernel<<<blocks, 256, smem>>>(x, W, b, s_ptr, D, N);
    }

    // Kernel 2: dense coalesced combine
    combine_kernel<<<N, 256>>>(f, y_ptr, D);

    // Kernel 3: reductions + tail
    if (has_metrics || tail_n > 0) {
        reduce_kernel<<<1, 1024>>>(soft_ptr, hard_ptr, tail_ptr, tail_n, N);
    }
}

// round 12
// speedup vs baseline: 1.8021x; 1.1883x over previous
#include <cuda_runtime.h>
#include <math.h>

#define SPARSITY_EPS 1e-05f
#define MAX_N 65536

// Per-token routing record: {e0 (int bits), e1 (int bits), w0, w1}
__device__ float4 g_rec[MAX_N];

// ---------------------------------------------------------------------------
// Kernel 1: gate, specialized E==16, D%128==0.
// 2 tokens per warp, 8 warps/block. W (48KB) staged in dynamic smem.
// ZERO static smem (48KB dynamic is the per-block cap without opt-in).
// Distributed butterfly reduction, then shfl-gather of logits (no smem).
// ---------------------------------------------------------------------------
__global__ __launch_bounds__(256) void gate_kernel_fast(
    const float* __restrict__ x,
    const float* __restrict__ W,
    const float* __restrict__ b,
    float* __restrict__ s_out,   // may be null
    int D, int N)
{
    extern __shared__ float4 ws4[];          // [16 * D/4] == 48KB for D=768

    const int tid  = threadIdx.x;
    const int lane = tid & 31;
    const int wid  = tid >> 5;
    const int D4   = D >> 2;

    // stage W as float4, coalesced
    const float4* Wg4 = (const float4*)W;
    for (int i = tid; i < 16 * D4; i += blockDim.x) ws4[i] = Wg4[i];
    __syncthreads();

    const int n0 = (blockIdx.x * 8 + wid) * 2;
    const int n1 = n0 + 1;
    if (n0 >= N) return;
    const bool has1 = (n1 < N);

    float a0[16], a1[16];
    #pragma unroll
    for (int e = 0; e < 16; e++) { a0[e] = 0.f; a1[e] = 0.f; }

    const float4* xr0 = (const float4*)(x + (size_t)n0 * D);
    const float4* xr1 = (const float4*)(x + (size_t)(has1 ? n1 : n0) * D);
    const int iters = D4 >> 5;               // D/128
    for (int i = 0; i < iters; i++) {
        const int q = lane + (i << 5);
        float4 x0 = xr0[q];
        float4 x1 = xr1[q];
        #pragma unroll
        for (int e = 0; e < 16; e++) {
            float4 wv = ws4[e * D4 + q];
            a0[e] += x0.x * wv.x + x0.y * wv.y + x0.z * wv.z + x0.w * wv.w;
            a1[e] += x1.x * wv.x + x1.y * wv.y + x1.z * wv.z + x1.w * wv.w;
        }
    }

    // distributed reduction: 16 values x 32 lanes.
    // After 4 halving steps + final pair-add, lane l holds the full sum
    // for expert (l >> 1) in a0[0] / a1[0].
    #pragma unroll
    for (int s = 0; s < 4; s++) {
        const int off = 16 >> s;
        const int cnt = 8 >> s;
        const bool hi = (lane & off) != 0;
        #pragma unroll
        for (int j = 0; j < 8; j++) {
            if (j < cnt) {
                float send0 = hi ? a0[j] : a0[j + cnt];
                float send1 = hi ? a1[j] : a1[j + cnt];
                float recv0 = __shfl_xor_sync(0xffffffffu, send0, off);
                float recv1 = __shfl_xor_sync(0xffffffffu, send1, off);
                float keep0 = hi ? a0[j + cnt] : a0[j];
                float keep1 = hi ? a1[j + cnt] : a1[j];
                a0[j] = keep0 + recv0;
                a1[j] = keep1 + recv1;
            }
        }
    }
    a0[0] += __shfl_xor_sync(0xffffffffu, a0[0], 1);
    a1[0] += __shfl_xor_sync(0xffffffffu, a1[0], 1);

    // gather all 16 expert logits into every lane via shuffles (no smem)
    float lg0[16], lg1[16];
    #pragma unroll
    for (int e = 0; e < 16; e++) {
        lg0[e] = __shfl_sync(0xffffffffu, a0[0], e * 2);
        lg1[e] = __shfl_sync(0xffffffffu, a1[0], e * 2);
    }

    // lane 0: top-2 + softmax for both tokens (add bias here)
    #pragma unroll
    for (int t = 0; t < 2; t++) {
        const int n = (t == 0) ? n0 : n1;
        if (t == 1 && !has1) break;
        int e0 = 0, e1 = -1;
        float w0 = 0.f, w1 = 0.f;
        if (lane == 0) {
            float lg[16];
            #pragma unroll
            for (int e = 0; e < 16; e++)
                lg[e] = ((t == 0) ? lg0[e] : lg1[e]) + b[e];
            float v0 = lg[0]; e0 = 0;
            #pragma unroll
            for (int e = 1; e < 16; e++)
                if (lg[e] > v0) { v0 = lg[e]; e0 = e; }
            float v1 = -INFINITY;
            #pragma unroll
            for (int e = 0; e < 16; e++)
                if (e != e0 && lg[e] > v1) { v1 = lg[e]; e1 = e; }
            float ex = expf(v1 - v0);
            w0 = 1.0f / (1.0f + ex);
            w1 = ex / (1.0f + ex);
            g_rec[n] = make_float4(__int_as_float(e0), __int_as_float(e1), w0, w1);
        }
        e0 = __shfl_sync(0xffffffffu, e0, 0);
        e1 = __shfl_sync(0xffffffffu, e1, 0);
        w0 = __shfl_sync(0xffffffffu, w0, 0);
        w1 = __shfl_sync(0xffffffffu, w1, 0);
        if (s_out != nullptr && lane < 16) {
            float g = (lane == e0) ? w0 : ((lane == e1) ? w1 : 0.f);
            s_out[(size_t)n * 16 + lane] = (g < SPARSITY_EPS) ? 1.0f : 0.0f;
        }
    }
}

// ---------------------------------------------------------------------------
// Kernel 2: dense coalesced combine, fully unrolled. One block per token.
// ITER = D*16/4/256 float4 iterations per thread, loads front-batched.
// ---------------------------------------------------------------------------
template <int ITER>
__global__ __launch_bounds__(256) void combine_kernel_t(
    const float* __restrict__ f,
    float* __restrict__ y,
    int D)
{
    __shared__ float4 gq[4];                 // gate vector as 4 quads
    const int n   = blockIdx.x;
    const int tid = threadIdx.x;

    if (tid < 16) ((float*)gq)[tid] = 0.f;
    __syncthreads();
    if (tid == 0) {
        float4 r = g_rec[n];
        ((float*)gq)[__float_as_int(r.x)] = r.z;
        ((float*)gq)[__float_as_int(r.y)] = r.w;
    }
    __syncthreads();

    const float4* fb = (const float4*)(f + (size_t)n * D * 16);
    float* yrow = y + (size_t)n * D;

    // front-batch all loads -> MLP = ITER
    float4 fr[ITER];
    #pragma unroll
    for (int k = 0; k < ITER; k++)
        fr[k] = fb[tid + k * 256];

    const float4 g = gq[tid & 3];            // 256 % 4 == 0 -> invariant
    float p[ITER];
    #pragma unroll
    for (int k = 0; k < ITER; k++)
        p[k] = fr[k].x * g.x + fr[k].y * g.y + fr[k].z * g.z + fr[k].w * g.w;

    #pragma unroll
    for (int k = 0; k < ITER; k++) {
        p[k] += __shfl_xor_sync(0xffffffffu, p[k], 1);
        p[k] += __shfl_xor_sync(0xffffffffu, p[k], 2);
    }

    if ((tid & 3) == 0) {
        #pragma unroll
        for (int k = 0; k < ITER; k++)
            yrow[(tid >> 2) + k * 64] = p[k];
    }
}

// generic fallback combine (any D, E==16)
__global__ void combine_kernel_gen(const float* __restrict__ f,
                                   float* __restrict__ y, int D)
{
    __shared__ float4 gq[4];
    const int n   = blockIdx.x;
    const int tid = threadIdx.x;
    if (tid < 16) ((float*)gq)[tid] = 0.f;
    __syncthreads();
    if (tid == 0) {
        float4 r = g_rec[n];
        ((float*)gq)[__float_as_int(r.x)] = r.z;
        ((float*)gq)[__float_as_int(r.y)] = r.w;
    }
    __syncthreads();
    const int total4 = D << 2;
    const float4* fb = (const float4*)(f + (size_t)n * D * 16);
    float* yrow = y + (size_t)n * D;
    for (int i = tid; i < total4; i += blockDim.x) {
        float4 fv = fb[i];
        float4 g  = gq[i & 3];
        float p = fv.x * g.x + fv.y * g.y + fv.z * g.z + fv.w * g.w;
        p += __shfl_xor_sync(0xffffffffu, p, 1);
        p += __shfl_xor_sync(0xffffffffu, p, 2);
        if ((tid & 3) == 0) yrow[i >> 2] = p;
    }
}

// ---------------------------------------------------------------------------
// Kernel 3: reductions for soft/hard averages + tail zeroing. Deterministic.
// ---------------------------------------------------------------------------
__global__ void reduce_kernel(float* __restrict__ soft_out,
                              float* __restrict__ hard_out,
                              float* __restrict__ tail,
                              int tail_n, int N)
{
    __shared__ float s_soft[32 * 16];
    __shared__ float s_hard[32 * 16];
    const int tid  = threadIdx.x;
    const int lane = tid & 31;
    const int wid  = tid >> 5;

    if (soft_out != nullptr) {
        float lsoft[16], lhard[16];
        #pragma unroll
        for (int e = 0; e < 16; e++) { lsoft[e] = 0.f; lhard[e] = 0.f; }

        for (int n = tid; n < N; n += blockDim.x) {
            float4 r = g_rec[n];
            int e0 = __float_as_int(r.x);
            int e1 = __float_as_int(r.y);
            lsoft[e0] += r.z;
            if (r.z >= SPARSITY_EPS) lhard[e0] += 1.f;
            lsoft[e1] += r.w;
            if (r.w >= SPARSITY_EPS) lhard[e1] += 1.f;
        }
        #pragma unroll
        for (int off = 16; off; off >>= 1) {
            #pragma unroll
            for (int e = 0; e < 16; e++) {
                lsoft[e] += __shfl_xor_sync(0xffffffffu, lsoft[e], off);
                lhard[e] += __shfl_xor_sync(0xffffffffu, lhard[e], off);
            }
        }
        if (lane == 0) {
            #pragma unroll
            for (int e = 0; e < 16; e++) {
                s_soft[wid * 16 + e] = lsoft[e];
                s_hard[wid * 16 + e] = lhard[e];
            }
        }
        __syncthreads();
        if (tid < 16) {
            float ss = 0.f, hh = 0.f;
            const int nw = blockDim.x >> 5;
            for (int w = 0; w < nw; w++) {
                ss += s_soft[w * 16 + tid];
                hh += s_hard[w * 16 + tid];
            }
            float invN = 1.0f / (float)N;
            soft_out[tid] = ss * invN;
            hard_out[tid] = hh * invN;
        }
    }

    if (tail != nullptr) {
        for (int i = tid; i < tail_n; i += blockDim.x) tail[i] = 0.0f;
    }
}

// ---------------------------------------------------------------------------
extern "C" void kernel_launch(void* const* d_in, const int* in_sizes, int n_in,
                              void* d_out, int out_size)
{
    const float* f = (const float*)d_in[0];   // [N, D, E]
    const float* x = (const float*)d_in[1];   // [N, D]
    const float* W = (const float*)d_in[2];   // [E, D]
    const float* b = (const float*)d_in[3];   // [E]

    const int E = in_sizes[3];                // 16
    const int D = in_sizes[2] / E;            // 768
    const int N = in_sizes[1] / D;            // 8192

    float* out = (float*)d_out;

    const long long y_elems    = (long long)N * D;
    const long long full_elems = y_elems + 2LL * E + (long long)N * E;
    const bool has_metrics = ((long long)out_size >= full_elems);

    float* y_ptr    = out;
    float* soft_ptr = has_metrics ? out + y_elems : nullptr;
    float* hard_ptr = has_metrics ? out + y_elems + E : nullptr;
    float* s_ptr    = has_metrics ? out + y_elems + 2 * E : nullptr;
    float* tail_ptr = nullptr;
    int    tail_n   = 0;
    if (has_metrics && (long long)out_size > full_elems) {
        tail_ptr = out + full_elems;
        tail_n   = (int)((long long)out_size - full_elems);
    } else if (!has_metrics && (long long)out_size > y_elems) {
        tail_ptr = out + y_elems;
        tail_n   = (int)((long long)out_size - y_elems);
    }

    // Kernel 1: gate (E==16, D%128==0 assumed per problem shape)
    // dynamic smem = 16*D*4 bytes = 48KB for D=768 (exactly the default cap,
    // zero static smem in the kernel).
    {
        size_t smem = (size_t)(16 * D) * sizeof(float);
        int blocks = (N + 15) / 16;           // 2 tokens/warp, 8 warps/block
        gate_kernel_fast<<<blocks, 256, smem>>>(x, W, b, s_ptr, D, N);
    }

    // Kernel 2: combine
    if (D == 768) {
        combine_kernel_t<12><<<N, 256>>>(f, y_ptr, D);
    } else if (D == 1024) {
        combine_kernel_t<16><<<N, 256>>>(f, y_ptr, D);
    } else if (D == 512) {
        combine_kernel_t<8><<<N, 256>>>(f, y_ptr, D);
    } else {
        combine_kernel_gen<<<N, 256>>>(f, y_ptr, D);
    }

    // Kernel 3: reductions + tail
    if (has_metrics || tail_n > 0) {
        reduce_kernel<<<1, 1024>>>(soft_ptr, hard_ptr, tail_ptr, tail_n, N);
    }
}